// round 1
// baseline (speedup 1.0000x reference)
#include <cuda_runtime.h>

#define K_DIM 512
#define N_DIM 512
#define BM 128
#define BN 128
#define BK 16
#define TM 8
#define TN 8

// Scratch (allocation-free): quantized weight, transposed to [K][N] so the
// GEMM reads B rows contiguously; quantized bias as exact integer-valued floats.
__device__ float g_wqT[K_DIM * N_DIM];
__device__ float g_bq[N_DIM];

// One block per output channel: max-abs reduce over the 512 input weights,
// per-channel symmetric quant (scale = max(|w|, EPS)/127), store w_q transposed,
// compute b_q = clip(round(bias/ (scale_w*scale_x))), optionally emit scale_out.
__global__ void quant_weight_kernel(const float* __restrict__ weight,
                                    const float* __restrict__ bias,
                                    const float* __restrict__ scale_x,
                                    float* __restrict__ scale_out_dst,
                                    int write_scale) {
    __shared__ float red[256];
    const int o = blockIdx.x;
    const float* wrow = weight + o * K_DIM;

    float m = 0.0f;
    for (int k = threadIdx.x; k < K_DIM; k += 256)
        m = fmaxf(m, fabsf(wrow[k]));
    red[threadIdx.x] = m;
    __syncthreads();
    for (int s = 128; s > 0; s >>= 1) {
        if (threadIdx.x < s)
            red[threadIdx.x] = fmaxf(red[threadIdx.x], red[threadIdx.x + s]);
        __syncthreads();
    }
    // max(|min|,|max|) == max|w|
    const float scale = fmaxf(red[0], 1e-8f) / 127.0f;
    const float inv_scale = 1.0f / scale;

    for (int k = threadIdx.x; k < K_DIM; k += 256) {
        float q = rintf(wrow[k] * inv_scale);   // rintf = round-half-even, matches jnp.round
        q = fminf(fmaxf(q, -128.0f), 127.0f);
        g_wqT[k * N_DIM + o] = q;
    }

    if (threadIdx.x == 0) {
        const float so = scale * scale_x[0];
        float bq = rintf(bias[o] / so);
        // int32 clip (values here are tiny; clamp is a formality)
        bq = fminf(fmaxf(bq, -2147483648.0f), 2147483520.0f);
        g_bq[o] = bq;
        if (write_scale) scale_out_dst[o] = so;
    }
}

// Classic register-blocked SGEMM: C[M,N] = A[M,K] * B[K,N] + bias.
// A = x_q (integer-valued fp32), B = g_wqT. All arithmetic exact (< 2^24).
__global__ __launch_bounds__(256) void gemm_kernel(const float* __restrict__ A,
                                                   float* __restrict__ C) {
    __shared__ float As[BK][BM];
    __shared__ float Bs[BK][BN];

    const int bx = blockIdx.x;          // N tile index
    const int by = blockIdx.y;          // M tile index
    const int tid = threadIdx.x;
    const int tx = tid & 15;            // 16 threads across N
    const int ty = tid >> 4;            // 16 threads across M

    const float* Ab = A + (size_t)by * BM * K_DIM;
    const float* Bb = g_wqT + bx * BN;

    float acc[TM][TN] = {};

    for (int kb = 0; kb < K_DIM; kb += BK) {
        // Load A tile 128x16 (512 float4; 2 per thread), transpose into As[k][m]
        #pragma unroll
        for (int i = 0; i < 2; i++) {
            int idx = tid + i * 256;                 // 0..511
            int row = idx >> 2;                      // 0..127
            int c4  = idx & 3;                       // float4 index within row
            float4 v = *(const float4*)(Ab + (size_t)row * K_DIM + kb + c4 * 4);
            As[c4 * 4 + 0][row] = v.x;
            As[c4 * 4 + 1][row] = v.y;
            As[c4 * 4 + 2][row] = v.z;
            As[c4 * 4 + 3][row] = v.w;
        }
        // Load B tile 16x128 (512 float4; 2 per thread), direct copy
        #pragma unroll
        for (int i = 0; i < 2; i++) {
            int idx = tid + i * 256;
            int row = idx >> 5;                      // 0..15
            int c4  = idx & 31;
            float4 v = *(const float4*)(Bb + (size_t)(kb + row) * N_DIM + c4 * 4);
            *(float4*)&Bs[row][c4 * 4] = v;
        }
        __syncthreads();

        #pragma unroll
        for (int k = 0; k < BK; k++) {
            float a[TM], b[TN];
            #pragma unroll
            for (int i = 0; i < TM; i++) a[i] = As[k][ty * TM + i];
            #pragma unroll
            for (int j = 0; j < TN; j++) b[j] = Bs[k][tx * TN + j];
            #pragma unroll
            for (int i = 0; i < TM; i++)
                #pragma unroll
                for (int j = 0; j < TN; j++)
                    acc[i][j] += a[i] * b[j];
        }
        __syncthreads();
    }

    // Epilogue: add quantized bias, store
    const int crow0 = by * BM + ty * TM;
    const int ccol0 = bx * BN + tx * TN;
    float bq[TN];
    #pragma unroll
    for (int j = 0; j < TN; j++) bq[j] = g_bq[ccol0 + j];

    #pragma unroll
    for (int i = 0; i < TM; i++) {
        #pragma unroll
        for (int j = 0; j < TN; j += 4) {
            float4 v = make_float4(acc[i][j + 0] + bq[j + 0],
                                   acc[i][j + 1] + bq[j + 1],
                                   acc[i][j + 2] + bq[j + 2],
                                   acc[i][j + 3] + bq[j + 3]);
            *(float4*)(C + (size_t)(crow0 + i) * N_DIM + ccol0 + j) = v;
        }
    }
}

extern "C" void kernel_launch(void* const* d_in, const int* in_sizes, int n_in,
                              void* d_out, int out_size) {
    const float* x_q     = (const float*)d_in[0];   // [M, 512]
    const float* weight  = (const float*)d_in[1];   // [512, 512]
    const float* bias    = (const float*)d_in[2];   // [512]
    const float* scale_x = (const float*)d_in[3];   // [1]
    float* out = (float*)d_out;

    const int M = in_sizes[0] / K_DIM;              // 65536

    // If the harness concatenates (out_q, scale_out), write scale_out at the tail.
    const long long need = (long long)M * N_DIM + N_DIM;
    const int write_scale = ((long long)out_size >= need) ? 1 : 0;

    quant_weight_kernel<<<N_DIM, 256>>>(weight, bias, scale_x,
                                        out + (size_t)M * N_DIM, write_scale);

    dim3 grid(N_DIM / BN, M / BM);
    gemm_kernel<<<grid, 256>>>(x_q, out);
}

// round 4
// speedup vs baseline: 3.3923x; 3.3923x over previous
#include <cuda_runtime.h>
#include <cuda_bf16.h>
#include <cstdint>

#define K_DIM 512
#define N_DIM 512
#define BM 128
#define BN 128
#define BK 32

// ---------------- scratch (allocation-free) ----------------
__device__ float g_bq[N_DIM];                                   // quantized bias (integer-valued fp32)
__device__ __align__(16) __nv_bfloat16 g_wq[N_DIM * K_DIM];     // w_q bf16, [N][K] K-major

// ---------------- helpers ----------------
__device__ __forceinline__ uint32_t smem_u32(const void* p) {
    uint32_t a;
    asm("{ .reg .u64 t; cvta.to.shared.u64 t, %1; cvt.u32.u64 %0, t; }" : "=r"(a) : "l"(p));
    return a;
}
__device__ __forceinline__ void cp_async16(uint32_t dst, const void* src) {
    asm volatile("cp.async.cg.shared.global [%0], [%1], 16;" :: "r"(dst), "l"(src) : "memory");
}
__device__ __forceinline__ void ldmatrix_x4(uint32_t* r, uint32_t addr) {
    asm volatile("ldmatrix.sync.aligned.m8n8.x4.shared.b16 {%0,%1,%2,%3}, [%4];"
                 : "=r"(r[0]), "=r"(r[1]), "=r"(r[2]), "=r"(r[3]) : "r"(addr));
}
__device__ __forceinline__ void mma_16816(float* d, const uint32_t* a, const uint32_t* b) {
    asm volatile("mma.sync.aligned.m16n8k16.row.col.f32.bf16.bf16.f32 "
                 "{%0,%1,%2,%3}, {%4,%5,%6,%7}, {%8,%9}, {%0,%1,%2,%3};"
                 : "+f"(d[0]), "+f"(d[1]), "+f"(d[2]), "+f"(d[3])
                 : "r"(a[0]), "r"(a[1]), "r"(a[2]), "r"(a[3]), "r"(b[0]), "r"(b[1]));
}

// ---------------- weight quantization (one block per output channel) ----------------
__global__ void quant_weight_kernel(const float* __restrict__ weight,
                                    const float* __restrict__ bias,
                                    const float* __restrict__ scale_x,
                                    float* __restrict__ scale_out_dst,
                                    int write_scale) {
    __shared__ float red[256];
    const int o = blockIdx.x;
    const float* wrow = weight + o * K_DIM;

    float m = 0.0f;
    for (int k = threadIdx.x; k < K_DIM; k += 256) m = fmaxf(m, fabsf(wrow[k]));
    red[threadIdx.x] = m;
    __syncthreads();
    for (int s = 128; s > 0; s >>= 1) {
        if (threadIdx.x < s) red[threadIdx.x] = fmaxf(red[threadIdx.x], red[threadIdx.x + s]);
        __syncthreads();
    }
    const float scale = fmaxf(red[0], 1e-8f) / 127.0f;
    const float inv_scale = 1.0f / scale;

    for (int k = threadIdx.x; k < K_DIM; k += 256) {
        float q = rintf(wrow[k] * inv_scale);             // round-half-even == jnp.round
        q = fminf(fmaxf(q, -128.0f), 127.0f);
        g_wq[o * K_DIM + k] = __float2bfloat16_rn(q);     // exact: small integer
    }
    if (threadIdx.x == 0) {
        const float so = scale * scale_x[0];
        float bq = rintf(bias[o] / so);
        bq = fminf(fmaxf(bq, -2147483648.0f), 2147483520.0f);
        g_bq[o] = bq;
        if (write_scale) scale_out_dst[o] = so;
    }
}

// ---------------- HMMA GEMM: C[M,512] = x_q * Wq^T + bq ----------------
// 256 threads, 8 warps as 2(M) x 4(N); warp tile 64x32; double-buffered BK=32.
__global__ __launch_bounds__(256, 1) void gemm_mma(const float* __restrict__ A,
                                                   float* __restrict__ C) {
    __shared__ __align__(1024) char smem[32768];   // A: 2 x 8KB @0, B: 2 x 8KB @16384
    const uint32_t sb = smem_u32(smem);
    const int tid = threadIdx.x, lane = tid & 31, w = tid >> 5;
    const int wm = w & 1, wn = w >> 1;
    const int mb = blockIdx.y * BM;
    const int nb = blockIdx.x * BN;

    // --- A global->reg staging: thread t covers row (t>>1), 16 floats at half (t&1)
    const int arow = tid >> 1, ahalf = tid & 1;
    const float* aptr = A + (size_t)(mb + arow) * K_DIM + ahalf * 16;
    // A STS dst (SW64 swizzle on 64B bf16 rows)
    const uint32_t arx = (arow * 8) & 0x30;
    const uint32_t adst0 = sb + arow * 64 + ((ahalf * 32) ^ arx);
    const uint32_t adst1 = sb + arow * 64 + ((ahalf * 32 + 16) ^ arx);

    // --- B cp.async: thread t covers n-row (t&127), 32B half (t>>7)
    const int bn = tid & 127, bh = tid >> 7;
    const char* bsrc = (const char*)g_wq + (size_t)(nb + bn) * (K_DIM * 2) + bh * 32;
    const uint32_t brx = (bn * 8) & 0x30;
    const uint32_t bdst0 = sb + 16384 + bn * 64 + ((bh * 32) ^ brx);
    const uint32_t bdst1 = sb + 16384 + bn * 64 + ((bh * 32 + 16) ^ brx);

    // --- fragment lane addressing
    const uint32_t afr = wm * 64 + (lane & 15);         // A row within tile (+ mi*16)
    const uint32_t afrx = (afr * 8) & 0x30;
    const uint32_t afkb = (lane >> 4) * 16;             // k-chunk select
    const uint32_t afbase = sb + afr * 64;
    const uint32_t bfr = wn * 32 + ((lane >> 4) << 3) + (lane & 7);  // B n-row (+ p*16)
    const uint32_t bfrx = (bfr * 8) & 0x30;
    const uint32_t bfkb = ((lane >> 3) & 1) * 16;
    const uint32_t bfbase = sb + 16384 + bfr * 64;

    float acc[4][4][4] = {};

    // prologue: B(0) cp.async, A(0) LDG
    cp_async16(bdst0, bsrc);
    cp_async16(bdst1, bsrc + 16);
    asm volatile("cp.async.commit_group;" ::: "memory");
    float4 ar0 = *(const float4*)(aptr + 0);
    float4 ar1 = *(const float4*)(aptr + 4);
    float4 ar2 = *(const float4*)(aptr + 8);
    float4 ar3 = *(const float4*)(aptr + 12);

    #pragma unroll 1
    for (int c = 0; c < 16; c++) {
        const uint32_t so = (uint32_t)(c & 1) * 8192;

        // STS A(c) (fp32 -> bf16x2 pairs)
        uint32_t p[8];
        asm("cvt.rn.bf16x2.f32 %0, %1, %2;" : "=r"(p[0]) : "f"(ar0.y), "f"(ar0.x));
        asm("cvt.rn.bf16x2.f32 %0, %1, %2;" : "=r"(p[1]) : "f"(ar0.w), "f"(ar0.z));
        asm("cvt.rn.bf16x2.f32 %0, %1, %2;" : "=r"(p[2]) : "f"(ar1.y), "f"(ar1.x));
        asm("cvt.rn.bf16x2.f32 %0, %1, %2;" : "=r"(p[3]) : "f"(ar1.w), "f"(ar1.z));
        asm("cvt.rn.bf16x2.f32 %0, %1, %2;" : "=r"(p[4]) : "f"(ar2.y), "f"(ar2.x));
        asm("cvt.rn.bf16x2.f32 %0, %1, %2;" : "=r"(p[5]) : "f"(ar2.w), "f"(ar2.z));
        asm("cvt.rn.bf16x2.f32 %0, %1, %2;" : "=r"(p[6]) : "f"(ar3.y), "f"(ar3.x));
        asm("cvt.rn.bf16x2.f32 %0, %1, %2;" : "=r"(p[7]) : "f"(ar3.w), "f"(ar3.z));
        asm volatile("st.shared.v4.b32 [%0], {%1,%2,%3,%4};"
                     :: "r"(adst0 + so), "r"(p[0]), "r"(p[1]), "r"(p[2]), "r"(p[3]) : "memory");
        asm volatile("st.shared.v4.b32 [%0], {%1,%2,%3,%4};"
                     :: "r"(adst1 + so), "r"(p[4]), "r"(p[5]), "r"(p[6]), "r"(p[7]) : "memory");

        asm volatile("cp.async.wait_group 0;" ::: "memory");
        __syncthreads();

        if (c < 15) {
            const uint32_t so1 = (uint32_t)((c + 1) & 1) * 8192;
            const float* ap = aptr + (c + 1) * 32;
            ar0 = *(const float4*)(ap + 0);
            ar1 = *(const float4*)(ap + 4);
            ar2 = *(const float4*)(ap + 8);
            ar3 = *(const float4*)(ap + 12);
            const char* bp = bsrc + (c + 1) * 64;
            cp_async16(bdst0 + so1, bp);
            cp_async16(bdst1 + so1, bp + 16);
            asm volatile("cp.async.commit_group;" ::: "memory");
        }

        // compute stage s: 2 x k16 steps
        #pragma unroll
        for (int kk = 0; kk < 2; kk++) {
            uint32_t af[4][4], bf[2][4];
            #pragma unroll
            for (int mi = 0; mi < 4; mi++)
                ldmatrix_x4(af[mi], afbase + so + mi * 1024 + ((kk * 32 + afkb) ^ afrx));
            #pragma unroll
            for (int pq = 0; pq < 2; pq++)
                ldmatrix_x4(bf[pq], bfbase + so + pq * 1024 + ((kk * 32 + bfkb) ^ bfrx));
            #pragma unroll
            for (int mi = 0; mi < 4; mi++)
                #pragma unroll
                for (int ni = 0; ni < 4; ni++)
                    mma_16816(acc[mi][ni], af[mi], &bf[ni >> 1][(ni & 1) * 2]);
        }
        __syncthreads();
    }

    // ---------------- epilogue: +bias, direct float2 stores ----------------
    const int mrow = mb + wm * 64 + (lane >> 2);
    const int ncol = nb + wn * 32 + (lane & 3) * 2;
    #pragma unroll
    for (int ni = 0; ni < 4; ni++) {
        const float2 bq = *(const float2*)&g_bq[ncol + ni * 8];
        #pragma unroll
        for (int mi = 0; mi < 4; mi++) {
            const int r0 = mrow + mi * 16;
            float2 v0 = make_float2(acc[mi][ni][0] + bq.x, acc[mi][ni][1] + bq.y);
            float2 v1 = make_float2(acc[mi][ni][2] + bq.x, acc[mi][ni][3] + bq.y);
            *(float2*)(C + (size_t)r0 * N_DIM + ncol + ni * 8) = v0;
            *(float2*)(C + (size_t)(r0 + 8) * N_DIM + ncol + ni * 8) = v1;
        }
    }
}

// ---------------- launch ----------------
extern "C" void kernel_launch(void* const* d_in, const int* in_sizes, int n_in,
                              void* d_out, int out_size) {
    const float* x_q     = (const float*)d_in[0];   // [M, 512]
    const float* weight  = (const float*)d_in[1];   // [512, 512]
    const float* bias    = (const float*)d_in[2];   // [512]
    const float* scale_x = (const float*)d_in[3];   // [1]
    float* out = (float*)d_out;

    const int M = in_sizes[0] / K_DIM;
    const long long need = (long long)M * N_DIM + N_DIM;
    const int write_scale = ((long long)out_size >= need) ? 1 : 0;

    quant_weight_kernel<<<N_DIM, 256>>>(weight, bias, scale_x,
                                        out + (size_t)M * N_DIM, write_scale);

    dim3 grid(N_DIM / BN, M / BM);
    gemm_mma<<<grid, 256>>>(x_q, out);
}